// round 4
// baseline (speedup 1.0000x reference)
#include <cuda_runtime.h>
#include <cuda_bf16.h>
#include <cstdint>

#define NN 100000
#define EE 1600000
#define DD 128
#define LN_EPS 1e-5f
#define SCAN_BLK 1024
#define NB ((NN + SCAN_BLK - 1) / SCAN_BLK)   // 98

// ---------------- scratch (no allocs allowed) ----------------
__device__ float g_h[(size_t)NN * DD];    // current node features
__device__ float g_agg[(size_t)NN * DD];  // mean-aggregated feats / MLP hidden
__device__ float g_inv[NN];               // 1/deg (0 if deg==0)
__device__ int   g_rowptr[NN + 1];
__device__ int   g_cursor[NN];            // deg counter, then fill cursor
__device__ int   g_col[EE];
__device__ int   g_blocksum[128];
__device__ int   g_is64;                  // edge_index dtype flag

// ---------------- edge dtype detection ----------------
// int64 little-endian with values < 2^31: every odd 32-bit word is 0.
// int32: odd words are real node indices (nonzero w.p. ~1 over 2048 samples).
__global__ __launch_bounds__(1024) void k_detect(const unsigned* __restrict__ w) {
    __shared__ unsigned s[1024];
    int tid = threadIdx.x;
    unsigned v = 0;
    // scan odd words among the first 4096 words (16 KB, safe for either dtype)
#pragma unroll
    for (int i = 0; i < 2; i++) {
        int idx = 2 * (tid + i * 1024) + 1;
        v |= w[idx];
    }
    s[tid] = v;
    __syncthreads();
    for (int off = 512; off > 0; off >>= 1) {
        if (tid < off) s[tid] |= s[tid + off];
        __syncthreads();
    }
    if (tid == 0) g_is64 = (s[0] == 0u) ? 1 : 0;
}

__device__ __forceinline__ int edge_at(const void* ei, size_t idx) {
    int v;
    if (g_is64) v = (int)((const long long*)ei)[idx];
    else        v = ((const int*)ei)[idx];
    // clamp: turns any residual dtype surprise into rel_err, not a crash
    v = (v < 0) ? 0 : (v >= NN ? NN - 1 : v);
    return v;
}

// ---------------- CSR build ----------------
__global__ void k_deg_zero() {
    int i = blockIdx.x * blockDim.x + threadIdx.x;
    if (i < NN) g_cursor[i] = 0;
}

__global__ void k_deg_count(const void* __restrict__ ei) {
    int e = blockIdx.x * blockDim.x + threadIdx.x;
    if (e < EE) atomicAdd(&g_cursor[edge_at(ei, (size_t)EE + e)], 1);
}

// per-block inclusive scan of degrees into g_rowptr[i+1]; block sums out
__global__ __launch_bounds__(SCAN_BLK) void k_scan_block() {
    __shared__ int s[SCAN_BLK];
    int tid = threadIdx.x;
    int i = blockIdx.x * SCAN_BLK + tid;
    int v = (i < NN) ? g_cursor[i] : 0;
    s[tid] = v;
    __syncthreads();
#pragma unroll
    for (int off = 1; off < SCAN_BLK; off <<= 1) {
        int t = (tid >= off) ? s[tid - off] : 0;
        __syncthreads();
        s[tid] += t;
        __syncthreads();
    }
    if (i < NN) g_rowptr[i + 1] = s[tid];
    if (tid == SCAN_BLK - 1) g_blocksum[blockIdx.x] = s[tid];
}

__global__ void k_scan_sums() {
    if (threadIdx.x == 0 && blockIdx.x == 0) {
        int run = 0;
        for (int b = 0; b < NB; b++) {
            int t = g_blocksum[b];
            g_blocksum[b] = run;
            run += t;
        }
    }
}

// add block prefixes, compute inv_deg, reset cursors
__global__ void k_scan_finalize() {
    int i = blockIdx.x * blockDim.x + threadIdx.x;
    if (i >= NN) return;
    int d = g_cursor[i];
    g_inv[i] = (d > 0) ? (1.0f / (float)d) : 0.0f;
    g_rowptr[i + 1] += g_blocksum[i >> 10];
    if (i == 0) g_rowptr[0] = 0;
    g_cursor[i] = 0;
}

__global__ void k_fill(const void* __restrict__ ei) {
    int e = blockIdx.x * blockDim.x + threadIdx.x;
    if (e >= EE) return;
    int dst = edge_at(ei, (size_t)EE + e);
    int src = edge_at(ei, (size_t)e);
    int pos = g_rowptr[dst] + atomicAdd(&g_cursor[dst], 1);
    g_col[pos] = src;
}

// ---------------- pull-mode mean aggregation (warp per node) ---------------
// g_agg[n] = inv_deg[n] * sum_{j in N(n)} hin[j]
__global__ __launch_bounds__(256) void k_aggregate(const float* __restrict__ xin,
                                                   int use_gh) {
    int warp = (blockIdx.x * blockDim.x + threadIdx.x) >> 5;
    int lane = threadIdx.x & 31;
    if (warp >= NN) return;
    const float* hin = use_gh ? g_h : xin;
    int start = g_rowptr[warp];
    int end = g_rowptr[warp + 1];
    float4 acc = make_float4(0.f, 0.f, 0.f, 0.f);
    for (int j = start; j < end; j++) {
        int src = g_col[j];   // lane-uniform broadcast load
        float4 v = ((const float4*)(hin + (size_t)src * DD))[lane];
        acc.x += v.x; acc.y += v.y; acc.z += v.z; acc.w += v.w;
    }
    float inv = g_inv[warp];
    acc.x *= inv; acc.y *= inv; acc.z *= inv; acc.w *= inv;
    ((float4*)(g_agg + (size_t)warp * DD))[lane] = acc;
}

// ---------------- fused SAGE layer GEMM + bias + LayerNorm + SiLU ----------
// g_h = SiLU(LN( g_agg @ Wl^T + h_in @ Wr^T + bl + br ))
#define BM 64
#define BN 128
#define BK 16
#define TM 8
#define TN 4

__global__ __launch_bounds__(256) void k_layer(
    const float* __restrict__ xin, int use_gh,
    const float* __restrict__ Wl, const float* __restrict__ bl,
    const float* __restrict__ Wr, const float* __restrict__ br,
    const float* __restrict__ lng, const float* __restrict__ lnb) {
    __shared__ float As[BK][BM];
    __shared__ float Bs[BK][BN];
    __shared__ float Cs[BM][BN];
    __shared__ float bias_s[BN];

    const float* h_in = use_gh ? g_h : xin;
    const int tid = threadIdx.x;
    const int block_m = blockIdx.x * BM;

    if (tid < BN) bias_s[tid] = bl[tid] + br[tid];

    float acc[TM][TN];
#pragma unroll
    for (int i = 0; i < TM; i++)
#pragma unroll
        for (int j = 0; j < TN; j++) acc[i][j] = 0.f;

    const int tm0 = (tid >> 5) * TM;       // 0..56
    const int tn0 = (tid & 31) * TN;       // 0..124
    const int a_m = tid >> 2;              // 0..63
    const int a_k = (tid & 3) * 4;         // 0,4,8,12
    const int b_n = tid >> 1;              // 0..127
    const int b_k = (tid & 1) * 8;         // 0,8

    const int gm_a = block_m + a_m;

    for (int k0 = 0; k0 < 2 * DD; k0 += BK) {
        float4 av = make_float4(0.f, 0.f, 0.f, 0.f);
        if (gm_a < NN) {
            int k = k0 + a_k;
            if (k < DD)
                av = *(const float4*)(&g_agg[(size_t)gm_a * DD + k]);
            else
                av = *(const float4*)(h_in + (size_t)gm_a * DD + (k - DD));
        }
        const float* Wsrc = (k0 < DD) ? Wl : Wr;
        int kw = (k0 < DD) ? k0 : (k0 - DD);
        float4 bv0 = *(const float4*)(Wsrc + b_n * DD + kw + b_k);
        float4 bv1 = *(const float4*)(Wsrc + b_n * DD + kw + b_k + 4);

        __syncthreads();
        As[a_k + 0][a_m] = av.x;
        As[a_k + 1][a_m] = av.y;
        As[a_k + 2][a_m] = av.z;
        As[a_k + 3][a_m] = av.w;
        Bs[b_k + 0][b_n] = bv0.x;
        Bs[b_k + 1][b_n] = bv0.y;
        Bs[b_k + 2][b_n] = bv0.z;
        Bs[b_k + 3][b_n] = bv0.w;
        Bs[b_k + 4][b_n] = bv1.x;
        Bs[b_k + 5][b_n] = bv1.y;
        Bs[b_k + 6][b_n] = bv1.z;
        Bs[b_k + 7][b_n] = bv1.w;
        __syncthreads();

#pragma unroll
        for (int kk = 0; kk < BK; kk++) {
            float4 a0 = *(const float4*)&As[kk][tm0];
            float4 a1 = *(const float4*)&As[kk][tm0 + 4];
            float4 bf = *(const float4*)&Bs[kk][tn0];
            float af[TM] = {a0.x, a0.y, a0.z, a0.w, a1.x, a1.y, a1.z, a1.w};
            float bb[TN] = {bf.x, bf.y, bf.z, bf.w};
#pragma unroll
            for (int i = 0; i < TM; i++)
#pragma unroll
                for (int j = 0; j < TN; j++) acc[i][j] += af[i] * bb[j];
        }
    }

    __syncthreads();
#pragma unroll
    for (int i = 0; i < TM; i++) {
        float4 c;
        c.x = acc[i][0] + bias_s[tn0 + 0];
        c.y = acc[i][1] + bias_s[tn0 + 1];
        c.z = acc[i][2] + bias_s[tn0 + 2];
        c.w = acc[i][3] + bias_s[tn0 + 3];
        *(float4*)&Cs[tm0 + i][tn0] = c;
    }
    __syncthreads();

    const int warp = tid >> 5, lane = tid & 31;
    for (int r = warp; r < BM; r += 8) {
        int gm = block_m + r;
        if (gm >= NN) continue;  // warp-uniform
        float4 v = *(const float4*)&Cs[r][lane * 4];
        float s = v.x + v.y + v.z + v.w;
        float sq = v.x * v.x + v.y * v.y + v.z * v.z + v.w * v.w;
#pragma unroll
        for (int off = 16; off > 0; off >>= 1) {
            s += __shfl_xor_sync(0xffffffffu, s, off);
            sq += __shfl_xor_sync(0xffffffffu, sq, off);
        }
        float mu = s * (1.0f / DD);
        float var = sq * (1.0f / DD) - mu * mu;
        float rstd = rsqrtf(var + LN_EPS);
        float4 o;
        {
            float y = (v.x - mu) * rstd * lng[lane * 4 + 0] + lnb[lane * 4 + 0];
            o.x = y / (1.f + __expf(-y));
            y = (v.y - mu) * rstd * lng[lane * 4 + 1] + lnb[lane * 4 + 1];
            o.y = y / (1.f + __expf(-y));
            y = (v.z - mu) * rstd * lng[lane * 4 + 2] + lnb[lane * 4 + 2];
            o.z = y / (1.f + __expf(-y));
            y = (v.w - mu) * rstd * lng[lane * 4 + 3] + lnb[lane * 4 + 3];
            o.w = y / (1.f + __expf(-y));
        }
        *(float4*)&g_h[(size_t)gm * DD + lane * 4] = o;
    }
}

// ---------------- MLP layer 1: g_agg = relu(g_h @ W1^T + b1) ---------------
__global__ __launch_bounds__(256) void k_mlp1(const float* __restrict__ W1,
                                              const float* __restrict__ b1) {
    __shared__ float As[BK][BM];
    __shared__ float Bs[BK][BN];
    __shared__ float bias_s[BN];

    const int tid = threadIdx.x;
    const int block_m = blockIdx.x * BM;
    if (tid < BN) bias_s[tid] = b1[tid];

    float acc[TM][TN];
#pragma unroll
    for (int i = 0; i < TM; i++)
#pragma unroll
        for (int j = 0; j < TN; j++) acc[i][j] = 0.f;

    const int tm0 = (tid >> 5) * TM;
    const int tn0 = (tid & 31) * TN;
    const int a_m = tid >> 2;
    const int a_k = (tid & 3) * 4;
    const int b_n = tid >> 1;
    const int b_k = (tid & 1) * 8;
    const int gm_a = block_m + a_m;

    for (int k0 = 0; k0 < DD; k0 += BK) {
        float4 av = make_float4(0.f, 0.f, 0.f, 0.f);
        if (gm_a < NN) av = *(const float4*)(&g_h[(size_t)gm_a * DD + k0 + a_k]);
        float4 bv0 = *(const float4*)(W1 + b_n * DD + k0 + b_k);
        float4 bv1 = *(const float4*)(W1 + b_n * DD + k0 + b_k + 4);

        __syncthreads();
        As[a_k + 0][a_m] = av.x;
        As[a_k + 1][a_m] = av.y;
        As[a_k + 2][a_m] = av.z;
        As[a_k + 3][a_m] = av.w;
        Bs[b_k + 0][b_n] = bv0.x;
        Bs[b_k + 1][b_n] = bv0.y;
        Bs[b_k + 2][b_n] = bv0.z;
        Bs[b_k + 3][b_n] = bv0.w;
        Bs[b_k + 4][b_n] = bv1.x;
        Bs[b_k + 5][b_n] = bv1.y;
        Bs[b_k + 6][b_n] = bv1.z;
        Bs[b_k + 7][b_n] = bv1.w;
        __syncthreads();

#pragma unroll
        for (int kk = 0; kk < BK; kk++) {
            float4 a0 = *(const float4*)&As[kk][tm0];
            float4 a1 = *(const float4*)&As[kk][tm0 + 4];
            float4 bf = *(const float4*)&Bs[kk][tn0];
            float af[TM] = {a0.x, a0.y, a0.z, a0.w, a1.x, a1.y, a1.z, a1.w};
            float bb[TN] = {bf.x, bf.y, bf.z, bf.w};
#pragma unroll
            for (int i = 0; i < TM; i++)
#pragma unroll
                for (int j = 0; j < TN; j++) acc[i][j] += af[i] * bb[j];
        }
    }

#pragma unroll
    for (int i = 0; i < TM; i++) {
        int gm = block_m + tm0 + i;
        if (gm < NN) {
            float4 c;
            c.x = fmaxf(acc[i][0] + bias_s[tn0 + 0], 0.f);
            c.y = fmaxf(acc[i][1] + bias_s[tn0 + 1], 0.f);
            c.z = fmaxf(acc[i][2] + bias_s[tn0 + 2], 0.f);
            c.w = fmaxf(acc[i][3] + bias_s[tn0 + 3], 0.f);
            *(float4*)&g_agg[(size_t)gm * DD + tn0] = c;
        }
    }
}

// ---------------- MLP layer 2: out = g_agg @ w2 + b2 (warp per node) -------
__global__ __launch_bounds__(256) void k_mlp2(const float* __restrict__ w2,
                                              const float* __restrict__ b2,
                                              float* __restrict__ out) {
    int warp = (blockIdx.x * blockDim.x + threadIdx.x) >> 5;
    int lane = threadIdx.x & 31;
    if (warp >= NN) return;
    float4 h4 = *(const float4*)(&g_agg[(size_t)warp * DD + lane * 4]);
    float4 w4 = *(const float4*)(w2 + lane * 4);
    float s = h4.x * w4.x + h4.y * w4.y + h4.z * w4.z + h4.w * w4.w;
#pragma unroll
    for (int off = 16; off > 0; off >>= 1) s += __shfl_xor_sync(0xffffffffu, s, off);
    if (lane == 0) out[warp] = s + b2[0];
}

// ---------------- launch ----------------
extern "C" void kernel_launch(void* const* d_in, const int* in_sizes, int n_in,
                              void* d_out, int out_size) {
    const float* x = (const float*)d_in[0];
    const void* ei = d_in[1];
    const float* lin_l_w = (const float*)d_in[2];
    const float* lin_l_b = (const float*)d_in[3];
    const float* lin_r_w = (const float*)d_in[4];
    const float* lin_r_b = (const float*)d_in[5];
    const float* ln_g = (const float*)d_in[6];
    const float* ln_b = (const float*)d_in[7];
    const float* mlp_w1 = (const float*)d_in[8];
    const float* mlp_b1 = (const float*)d_in[9];
    const float* mlp_w2 = (const float*)d_in[10];
    const float* mlp_b2 = (const float*)d_in[11];
    float* out = (float*)d_out;

    const int T = 256;
    const int gemm_grid = (NN + BM - 1) / BM;
    const int node_warp_grid = (NN * 32 + T - 1) / T;

    // ---- edge dtype detection + CSR build (int atomics only) ----
    k_detect<<<1, 1024>>>((const unsigned*)ei);
    k_deg_zero<<<(NN + T - 1) / T, T>>>();
    k_deg_count<<<(EE + T - 1) / T, T>>>(ei);
    k_scan_block<<<NB, SCAN_BLK>>>();
    k_scan_sums<<<1, 32>>>();
    k_scan_finalize<<<(NN + T - 1) / T, T>>>();
    k_fill<<<(EE + T - 1) / T, T>>>(ei);

    // ---- layer 0: input = x ----
    k_aggregate<<<node_warp_grid, T>>>(x, 0);
    k_layer<<<gemm_grid, T>>>(x, 0, lin_l_w, lin_l_b, lin_r_w, lin_r_b,
                              ln_g, ln_b);

    // ---- layer 1: input = g_h ----
    k_aggregate<<<node_warp_grid, T>>>(x, 1);
    k_layer<<<gemm_grid, T>>>(x, 1,
                              lin_l_w + DD * DD, lin_l_b + DD,
                              lin_r_w + DD * DD, lin_r_b + DD,
                              ln_g + DD, ln_b + DD);

    // ---- MLP head ----
    k_mlp1<<<gemm_grid, T>>>(mlp_w1, mlp_b1);
    k_mlp2<<<node_warp_grid, T>>>(mlp_w2, mlp_b2, out);
}

// round 5
// speedup vs baseline: 1.6580x; 1.6580x over previous
#include <cuda_runtime.h>
#include <cuda_bf16.h>
#include <cstdint>

#define NN 100000
#define EE 1600000
#define DD 128
#define LN_EPS 1e-5f
#define SCAN_BLK 1024
#define NB ((NN + SCAN_BLK - 1) / SCAN_BLK)   // 98

// ---------------- scratch (no allocs allowed) ----------------
__device__ float g_h[(size_t)NN * DD];    // current node features
__device__ float g_agg[(size_t)NN * DD];  // mean-aggregated feats / MLP hidden
__device__ float g_inv[NN];               // 1/deg (0 if deg==0)
__device__ int   g_rowptr[NN + 1];
__device__ int   g_cursor[NN];            // deg counter, then fill cursor
__device__ int   g_col[EE];
__device__ int   g_blocksum[128];
__device__ int   g_is64;                  // edge_index dtype flag

// ---------------- edge dtype detection ----------------
__global__ __launch_bounds__(1024) void k_detect(const unsigned* __restrict__ w) {
    __shared__ unsigned s[1024];
    int tid = threadIdx.x;
    unsigned v = 0;
#pragma unroll
    for (int i = 0; i < 2; i++) {
        int idx = 2 * (tid + i * 1024) + 1;
        v |= w[idx];
    }
    s[tid] = v;
    __syncthreads();
    for (int off = 512; off > 0; off >>= 1) {
        if (tid < off) s[tid] |= s[tid + off];
        __syncthreads();
    }
    if (tid == 0) g_is64 = (s[0] == 0u) ? 1 : 0;
}

__device__ __forceinline__ int edge_at(const void* ei, size_t idx) {
    int v;
    if (g_is64) v = (int)((const long long*)ei)[idx];
    else        v = ((const int*)ei)[idx];
    v = (v < 0) ? 0 : (v >= NN ? NN - 1 : v);
    return v;
}

// ---------------- CSR build ----------------
__global__ void k_deg_zero() {
    int i = blockIdx.x * blockDim.x + threadIdx.x;
    if (i < NN) g_cursor[i] = 0;
}

__global__ void k_deg_count(const void* __restrict__ ei) {
    int e = blockIdx.x * blockDim.x + threadIdx.x;
    if (e < EE) atomicAdd(&g_cursor[edge_at(ei, (size_t)EE + e)], 1);
}

__global__ __launch_bounds__(SCAN_BLK) void k_scan_block() {
    __shared__ int s[SCAN_BLK];
    int tid = threadIdx.x;
    int i = blockIdx.x * SCAN_BLK + tid;
    int v = (i < NN) ? g_cursor[i] : 0;
    s[tid] = v;
    __syncthreads();
#pragma unroll
    for (int off = 1; off < SCAN_BLK; off <<= 1) {
        int t = (tid >= off) ? s[tid - off] : 0;
        __syncthreads();
        s[tid] += t;
        __syncthreads();
    }
    if (i < NN) g_rowptr[i + 1] = s[tid];
    if (tid == SCAN_BLK - 1) g_blocksum[blockIdx.x] = s[tid];
}

// parallel exclusive scan of the 98 block sums (one 128-thread block)
__global__ __launch_bounds__(128) void k_scan_sums() {
    __shared__ int s[128];
    int tid = threadIdx.x;
    int v = (tid < NB) ? g_blocksum[tid] : 0;
    s[tid] = v;
    __syncthreads();
#pragma unroll
    for (int off = 1; off < 128; off <<= 1) {
        int t = (tid >= off) ? s[tid - off] : 0;
        __syncthreads();
        s[tid] += t;
        __syncthreads();
    }
    if (tid < NB) g_blocksum[tid] = s[tid] - v;  // exclusive
}

__global__ void k_scan_finalize() {
    int i = blockIdx.x * blockDim.x + threadIdx.x;
    if (i >= NN) return;
    int d = g_cursor[i];
    g_inv[i] = (d > 0) ? (1.0f / (float)d) : 0.0f;
    g_rowptr[i + 1] += g_blocksum[i >> 10];
    if (i == 0) g_rowptr[0] = 0;
    g_cursor[i] = 0;
}

__global__ void k_fill(const void* __restrict__ ei) {
    int e = blockIdx.x * blockDim.x + threadIdx.x;
    if (e >= EE) return;
    int dst = edge_at(ei, (size_t)EE + e);
    int src = edge_at(ei, (size_t)e);
    int pos = g_rowptr[dst] + atomicAdd(&g_cursor[dst], 1);
    g_col[pos] = src;
}

// ---------------- pull-mode mean aggregation (warp per node) ---------------
__global__ __launch_bounds__(256) void k_aggregate(const float* __restrict__ xin,
                                                   int use_gh) {
    int warp = (blockIdx.x * blockDim.x + threadIdx.x) >> 5;
    int lane = threadIdx.x & 31;
    if (warp >= NN) return;
    const float* hin = use_gh ? g_h : xin;
    int start = g_rowptr[warp];
    int end = g_rowptr[warp + 1];
    float4 acc = make_float4(0.f, 0.f, 0.f, 0.f);
    for (int j = start; j < end; j++) {
        int src = g_col[j];   // lane-uniform broadcast load
        float4 v = ((const float4*)(hin + (size_t)src * DD))[lane];
        acc.x += v.x; acc.y += v.y; acc.z += v.z; acc.w += v.w;
    }
    float inv = g_inv[warp];
    acc.x *= inv; acc.y *= inv; acc.z *= inv; acc.w *= inv;
    ((float4*)(g_agg + (size_t)warp * DD))[lane] = acc;
}

// ---------------- tf32 tensor-core GEMM machinery ----------------
__device__ __forceinline__ unsigned f2tf32(float f) {
    unsigned u;
    asm("cvt.rna.tf32.f32 %0, %1;" : "=r"(u) : "f"(f));
    return u;
}

__device__ __forceinline__ void mma_tf32(float* d, const unsigned* a,
                                         const unsigned* b) {
    asm volatile(
        "mma.sync.aligned.m16n8k8.row.col.f32.tf32.tf32.f32 "
        "{%0,%1,%2,%3}, {%4,%5,%6,%7}, {%8,%9}, {%0,%1,%2,%3};"
        : "+f"(d[0]), "+f"(d[1]), "+f"(d[2]), "+f"(d[3])
        : "r"(a[0]), "r"(a[1]), "r"(a[2]), "r"(a[3]), "r"(b[0]), "r"(b[1]));
}

#define LDK 36  // padded smem row (floats): bank-conflict-free fragments

// ---- fused SAGE layer: g_h = SiLU(LN([g_agg | h_in] @ [Wl|Wr]^T + b)) ----
// block tile 128x128, 8 warps in 4(M) x 2(N), warp tile 32x64
__global__ __launch_bounds__(256) void k_layer_tc(
    const float* __restrict__ xin, int use_gh,
    const float* __restrict__ Wl, const float* __restrict__ bl,
    const float* __restrict__ Wr, const float* __restrict__ br,
    const float* __restrict__ lng, const float* __restrict__ lnb) {
    __shared__ unsigned As_[128 * LDK];
    __shared__ unsigned Bs_[128 * LDK];
    __shared__ float red_s[128][2][2];   // [row][warp_n][sum,sumsq]
    __shared__ float bias_s[128], lng_s[128], lnb_s[128];

    const float* h_in = use_gh ? g_h : xin;
    const int tid = threadIdx.x;
    const int block_m = blockIdx.x * 128;

    if (tid < 128) {
        bias_s[tid] = bl[tid] + br[tid];
        lng_s[tid] = lng[tid];
        lnb_s[tid] = lnb[tid];
    }

    const int wid = tid >> 5, lane = tid & 31;
    const int wm = wid >> 1, wn = wid & 1;
    const int g = lane >> 2, c = lane & 3;
    const int m_w = 32 * wm, n_w = 64 * wn;

    float d[2][8][4];
#pragma unroll
    for (int mt = 0; mt < 2; mt++)
#pragma unroll
        for (int nt = 0; nt < 8; nt++)
#pragma unroll
            for (int r = 0; r < 4; r++) d[mt][nt][r] = 0.f;

    for (int k0 = 0; k0 < 2 * DD; k0 += 32) {
        const float* Wsrc = (k0 < DD) ? Wl : Wr;
        const int kw0 = k0 & (DD - 1);
#pragma unroll
        for (int i = 0; i < 4; i++) {
            int idx = tid + 256 * i;
            int row = idx >> 3;
            int kq = (idx & 7) * 4;
            int gm = block_m + row;
            float4 av = make_float4(0.f, 0.f, 0.f, 0.f);
            if (gm < NN) {
                int k = k0 + kq;
                if (k < DD) av = *(const float4*)(&g_agg[(size_t)gm * DD + k]);
                else        av = *(const float4*)(h_in + (size_t)gm * DD + (k - DD));
            }
            unsigned* ap = &As_[row * LDK + kq];
            ap[0] = f2tf32(av.x); ap[1] = f2tf32(av.y);
            ap[2] = f2tf32(av.z); ap[3] = f2tf32(av.w);

            float4 wv = *(const float4*)(Wsrc + row * DD + kw0 + kq);
            unsigned* bp = &Bs_[row * LDK + kq];
            bp[0] = f2tf32(wv.x); bp[1] = f2tf32(wv.y);
            bp[2] = f2tf32(wv.z); bp[3] = f2tf32(wv.w);
        }
        __syncthreads();

#pragma unroll
        for (int ks = 0; ks < 4; ks++) {
            const int kk = ks * 8;
            unsigned a[2][4];
#pragma unroll
            for (int mt = 0; mt < 2; mt++) {
                int mr = m_w + 16 * mt + g;
                a[mt][0] = As_[mr * LDK + kk + c];
                a[mt][1] = As_[(mr + 8) * LDK + kk + c];
                a[mt][2] = As_[mr * LDK + kk + c + 4];
                a[mt][3] = As_[(mr + 8) * LDK + kk + c + 4];
            }
            unsigned bf[8][2];
#pragma unroll
            for (int nt = 0; nt < 8; nt++) {
                int n = n_w + 8 * nt + g;
                bf[nt][0] = Bs_[n * LDK + kk + c];
                bf[nt][1] = Bs_[n * LDK + kk + c + 4];
            }
#pragma unroll
            for (int mt = 0; mt < 2; mt++)
#pragma unroll
                for (int nt = 0; nt < 8; nt++)
                    mma_tf32(d[mt][nt], a[mt], bf[nt]);
        }
        __syncthreads();
    }

    // ---- epilogue: bias, LN (shuffle + cross-warp smem), SiLU, store ----
#pragma unroll
    for (int mt = 0; mt < 2; mt++) {
        float s0 = 0.f, q0 = 0.f, s1 = 0.f, q1 = 0.f;
#pragma unroll
        for (int nt = 0; nt < 8; nt++) {
            int col = n_w + 8 * nt + 2 * c;
            float b0 = bias_s[col], b1 = bias_s[col + 1];
            float v0 = d[mt][nt][0] + b0, v1 = d[mt][nt][1] + b1;
            float v2 = d[mt][nt][2] + b0, v3 = d[mt][nt][3] + b1;
            d[mt][nt][0] = v0; d[mt][nt][1] = v1;
            d[mt][nt][2] = v2; d[mt][nt][3] = v3;
            s0 += v0 + v1; q0 += v0 * v0 + v1 * v1;
            s1 += v2 + v3; q1 += v2 * v2 + v3 * v3;
        }
#pragma unroll
        for (int off = 1; off <= 2; off <<= 1) {
            s0 += __shfl_xor_sync(0xffffffffu, s0, off);
            q0 += __shfl_xor_sync(0xffffffffu, q0, off);
            s1 += __shfl_xor_sync(0xffffffffu, s1, off);
            q1 += __shfl_xor_sync(0xffffffffu, q1, off);
        }
        if (c == 0) {
            int r0 = m_w + 16 * mt + g;
            red_s[r0][wn][0] = s0; red_s[r0][wn][1] = q0;
            red_s[r0 + 8][wn][0] = s1; red_s[r0 + 8][wn][1] = q1;
        }
    }
    __syncthreads();

#pragma unroll
    for (int mt = 0; mt < 2; mt++) {
        int r0 = m_w + 16 * mt + g;
        int r1 = r0 + 8;
        float sum0 = red_s[r0][0][0] + red_s[r0][1][0];
        float ssq0 = red_s[r0][0][1] + red_s[r0][1][1];
        float sum1 = red_s[r1][0][0] + red_s[r1][1][0];
        float ssq1 = red_s[r1][0][1] + red_s[r1][1][1];
        float mu0 = sum0 * (1.0f / DD);
        float rs0 = rsqrtf(ssq0 * (1.0f / DD) - mu0 * mu0 + LN_EPS);
        float mu1 = sum1 * (1.0f / DD);
        float rs1 = rsqrtf(ssq1 * (1.0f / DD) - mu1 * mu1 + LN_EPS);
        int gm0 = block_m + r0, gm1 = block_m + r1;
#pragma unroll
        for (int nt = 0; nt < 8; nt++) {
            int col = n_w + 8 * nt + 2 * c;
            float gg0 = lng_s[col], gg1 = lng_s[col + 1];
            float bb0 = lnb_s[col], bb1 = lnb_s[col + 1];
            if (gm0 < NN) {
                float y0 = (d[mt][nt][0] - mu0) * rs0 * gg0 + bb0;
                float y1 = (d[mt][nt][1] - mu0) * rs0 * gg1 + bb1;
                y0 = y0 / (1.f + __expf(-y0));
                y1 = y1 / (1.f + __expf(-y1));
                *(float2*)&g_h[(size_t)gm0 * DD + col] = make_float2(y0, y1);
            }
            if (gm1 < NN) {
                float y2 = (d[mt][nt][2] - mu1) * rs1 * gg0 + bb0;
                float y3 = (d[mt][nt][3] - mu1) * rs1 * gg1 + bb1;
                y2 = y2 / (1.f + __expf(-y2));
                y3 = y3 / (1.f + __expf(-y3));
                *(float2*)&g_h[(size_t)gm1 * DD + col] = make_float2(y2, y3);
            }
        }
    }
}

// ---- MLP layer 1 (tensor core): g_agg = relu(g_h @ W1^T + b1) ----
__global__ __launch_bounds__(256) void k_mlp1_tc(const float* __restrict__ W1,
                                                 const float* __restrict__ b1) {
    __shared__ unsigned As_[128 * LDK];
    __shared__ unsigned Bs_[128 * LDK];
    __shared__ float bias_s[128];

    const int tid = threadIdx.x;
    const int block_m = blockIdx.x * 128;
    if (tid < 128) bias_s[tid] = b1[tid];

    const int wid = tid >> 5, lane = tid & 31;
    const int wm = wid >> 1, wn = wid & 1;
    const int g = lane >> 2, c = lane & 3;
    const int m_w = 32 * wm, n_w = 64 * wn;

    float d[2][8][4];
#pragma unroll
    for (int mt = 0; mt < 2; mt++)
#pragma unroll
        for (int nt = 0; nt < 8; nt++)
#pragma unroll
            for (int r = 0; r < 4; r++) d[mt][nt][r] = 0.f;

    for (int k0 = 0; k0 < DD; k0 += 32) {
#pragma unroll
        for (int i = 0; i < 4; i++) {
            int idx = tid + 256 * i;
            int row = idx >> 3;
            int kq = (idx & 7) * 4;
            int gm = block_m + row;
            float4 av = make_float4(0.f, 0.f, 0.f, 0.f);
            if (gm < NN) av = *(const float4*)(&g_h[(size_t)gm * DD + k0 + kq]);
            unsigned* ap = &As_[row * LDK + kq];
            ap[0] = f2tf32(av.x); ap[1] = f2tf32(av.y);
            ap[2] = f2tf32(av.z); ap[3] = f2tf32(av.w);

            float4 wv = *(const float4*)(W1 + row * DD + k0 + kq);
            unsigned* bp = &Bs_[row * LDK + kq];
            bp[0] = f2tf32(wv.x); bp[1] = f2tf32(wv.y);
            bp[2] = f2tf32(wv.z); bp[3] = f2tf32(wv.w);
        }
        __syncthreads();

#pragma unroll
        for (int ks = 0; ks < 4; ks++) {
            const int kk = ks * 8;
            unsigned a[2][4];
#pragma unroll
            for (int mt = 0; mt < 2; mt++) {
                int mr = m_w + 16 * mt + g;
                a[mt][0] = As_[mr * LDK + kk + c];
                a[mt][1] = As_[(mr + 8) * LDK + kk + c];
                a[mt][2] = As_[mr * LDK + kk + c + 4];
                a[mt][3] = As_[(mr + 8) * LDK + kk + c + 4];
            }
            unsigned bf[8][2];
#pragma unroll
            for (int nt = 0; nt < 8; nt++) {
                int n = n_w + 8 * nt + g;
                bf[nt][0] = Bs_[n * LDK + kk + c];
                bf[nt][1] = Bs_[n * LDK + kk + c + 4];
            }
#pragma unroll
            for (int mt = 0; mt < 2; mt++)
#pragma unroll
                for (int nt = 0; nt < 8; nt++)
                    mma_tf32(d[mt][nt], a[mt], bf[nt]);
        }
        __syncthreads();
    }

#pragma unroll
    for (int mt = 0; mt < 2; mt++) {
        int r0 = m_w + 16 * mt + g;
        int gm0 = block_m + r0, gm1 = gm0 + 8;
#pragma unroll
        for (int nt = 0; nt < 8; nt++) {
            int col = n_w + 8 * nt + 2 * c;
            float b0 = bias_s[col], b1 = bias_s[col + 1];
            if (gm0 < NN) {
                float v0 = fmaxf(d[mt][nt][0] + b0, 0.f);
                float v1 = fmaxf(d[mt][nt][1] + b1, 0.f);
                *(float2*)&g_agg[(size_t)gm0 * DD + col] = make_float2(v0, v1);
            }
            if (gm1 < NN) {
                float v2 = fmaxf(d[mt][nt][2] + b0, 0.f);
                float v3 = fmaxf(d[mt][nt][3] + b1, 0.f);
                *(float2*)&g_agg[(size_t)gm1 * DD + col] = make_float2(v2, v3);
            }
        }
    }
}

// ---------------- MLP layer 2: out = g_agg @ w2 + b2 (warp per node) -------
__global__ __launch_bounds__(256) void k_mlp2(const float* __restrict__ w2,
                                              const float* __restrict__ b2,
                                              float* __restrict__ out) {
    int warp = (blockIdx.x * blockDim.x + threadIdx.x) >> 5;
    int lane = threadIdx.x & 31;
    if (warp >= NN) return;
    float4 h4 = *(const float4*)(&g_agg[(size_t)warp * DD + lane * 4]);
    float4 w4 = *(const float4*)(w2 + lane * 4);
    float s = h4.x * w4.x + h4.y * w4.y + h4.z * w4.z + h4.w * w4.w;
#pragma unroll
    for (int off = 16; off > 0; off >>= 1) s += __shfl_xor_sync(0xffffffffu, s, off);
    if (lane == 0) out[warp] = s + b2[0];
}

// ---------------- launch ----------------
extern "C" void kernel_launch(void* const* d_in, const int* in_sizes, int n_in,
                              void* d_out, int out_size) {
    const float* x = (const float*)d_in[0];
    const void* ei = d_in[1];
    const float* lin_l_w = (const float*)d_in[2];
    const float* lin_l_b = (const float*)d_in[3];
    const float* lin_r_w = (const float*)d_in[4];
    const float* lin_r_b = (const float*)d_in[5];
    const float* ln_g = (const float*)d_in[6];
    const float* ln_b = (const float*)d_in[7];
    const float* mlp_w1 = (const float*)d_in[8];
    const float* mlp_b1 = (const float*)d_in[9];
    const float* mlp_w2 = (const float*)d_in[10];
    const float* mlp_b2 = (const float*)d_in[11];
    float* out = (float*)d_out;

    const int T = 256;
    const int gemm_grid = (NN + 127) / 128;          // 782
    const int node_warp_grid = (NN * 32 + T - 1) / T;

    // ---- edge dtype detection + CSR build (int atomics only) ----
    k_detect<<<1, 1024>>>((const unsigned*)ei);
    k_deg_zero<<<(NN + T - 1) / T, T>>>();
    k_deg_count<<<(EE + T - 1) / T, T>>>(ei);
    k_scan_block<<<NB, SCAN_BLK>>>();
    k_scan_sums<<<1, 128>>>();
    k_scan_finalize<<<(NN + T - 1) / T, T>>>();
    k_fill<<<(EE + T - 1) / T, T>>>(ei);

    // ---- layer 0: input = x ----
    k_aggregate<<<node_warp_grid, T>>>(x, 0);
    k_layer_tc<<<gemm_grid, T>>>(x, 0, lin_l_w, lin_l_b, lin_r_w, lin_r_b,
                                 ln_g, ln_b);

    // ---- layer 1: input = g_h ----
    k_aggregate<<<node_warp_grid, T>>>(x, 1);
    k_layer_tc<<<gemm_grid, T>>>(x, 1,
                                 lin_l_w + DD * DD, lin_l_b + DD,
                                 lin_r_w + DD * DD, lin_r_b + DD,
                                 ln_g + DD, ln_b + DD);

    // ---- MLP head ----
    k_mlp1_tc<<<gemm_grid, T>>>(mlp_w1, mlp_b1);
    k_mlp2<<<node_warp_grid, T>>>(mlp_w2, mlp_b2, out);
}